// round 9
// baseline (speedup 1.0000x reference)
#include <cuda_runtime.h>
#include <cstdint>

#define BATCH 8
#define NPTS  8192
#define NS    2048      // S = 0.25 * N
#define KNB   32        // nsample
#define C1    64
#define C2    64
#define C3    128

// scratch: new_xyz coords shared between the two kernels
__device__ float g_new_xyz[BATCH * NS * 3];

// XLA-exact squared distance: ((dx*dx + dy*dy) + dz*dz), no FMA contraction
__device__ __forceinline__ float sqdist_xla(float dx, float dy, float dz) {
    return __fadd_rn(__fadd_rn(__fmul_rn(dx, dx), __fmul_rn(dy, dy)),
                     __fmul_rn(dz, dz));
}

__device__ __forceinline__ unsigned long long pack2(float a, float b) {
    unsigned long long r;
    asm("mov.b64 %0, {%1, %2};" : "=l"(r) : "f"(a), "f"(b));
    return r;
}
__device__ __forceinline__ void unpack2(unsigned long long v, float& a, float& b) {
    asm("mov.b64 {%0, %1}, %2;" : "=f"(a), "=f"(b) : "l"(v));
}
__device__ __forceinline__ unsigned long long add2(unsigned long long a, unsigned long long b) {
    unsigned long long r;
    asm("add.rn.f32x2 %0, %1, %2;" : "=l"(r) : "l"(a), "l"(b));
    return r;
}
__device__ __forceinline__ unsigned long long mul2(unsigned long long a, unsigned long long b) {
    unsigned long long r;
    asm("mul.rn.f32x2 %0, %1, %2;" : "=l"(r) : "l"(a), "l"(b));
    return r;
}
__device__ __forceinline__ unsigned long long fma2(unsigned long long a, unsigned long long b,
                                                   unsigned long long c) {
    unsigned long long r;
    asm("fma.rn.f32x2 %0, %1, %2, %3;" : "=l"(r) : "l"(a), "l"(b), "l"(c));
    return r;
}

// ---------------------------------------------------------------------------
// Kernel 1: farthest point sampling (R7 version — measured 1180us, at the
// single-SM fma-pipe issue floor). One CTA (256 threads) per batch.
// Phase A: f32x2 dist update (bit-exact rn), per-thread tree-fmax, warp max
// via REDUX.SYNC, leaders post to smem, block max computed by every thread.
// Phase B: only warps matching the block max recover the lowest matching
// global index (tree-min + REDUX.MIN + smem atomicMin) — exact jnp.argmax
// first-occurrence tie semantics.
// ---------------------------------------------------------------------------
__global__ __launch_bounds__(256) void fps_kernel(const float* __restrict__ xyz,
                                                  float* __restrict__ out)
{
    const int b   = blockIdx.x;
    const int tid = threadIdx.x;
    const int lane = tid & 31, wid = tid >> 5;
    const float* P = xyz + b * NPTS * 3;

    __shared__ int sVal[2][8];   // per-warp max (float bits)
    __shared__ int sIdx[2];      // block argmin index (atomicMin target)

    unsigned long long npx[16], npy[16], npz[16];
    float dist[32];
#pragma unroll
    for (int m = 0; m < 16; m++) {
        int i0 = tid + (2 * m) * 256;
        int i1 = tid + (2 * m + 1) * 256;
        npx[m] = pack2(-P[i0 * 3 + 0], -P[i1 * 3 + 0]);
        npy[m] = pack2(-P[i0 * 3 + 1], -P[i1 * 3 + 1]);
        npz[m] = pack2(-P[i0 * 3 + 2], -P[i1 * 3 + 2]);
        dist[2 * m] = 1e10f;
        dist[2 * m + 1] = 1e10f;
    }
    float cx = __ldg(P + 0), cy = __ldg(P + 1), cz = __ldg(P + 2);

    for (int s = 0; s < NS; s++) {
        const int pb = s & 1;
        if (tid == 0) {
            int o = b * 3 * NS + s;          // (B,3,S) transposed output
            out[o]          = cx;
            out[o + NS]     = cy;
            out[o + 2 * NS] = cz;
            int c = (b * NS + s) * 3;
            g_new_xyz[c]     = cx;
            g_new_xyz[c + 1] = cy;
            g_new_xyz[c + 2] = cz;
            sIdx[pb] = 0x7FFFFFFF;
        }

        const unsigned long long cxx = pack2(cx, cx);
        const unsigned long long cyy = pack2(cy, cy);
        const unsigned long long czz = pack2(cz, cz);

        // ---- dist update (bit-exact, no index tracking) ----
#pragma unroll
        for (int m = 0; m < 16; m++) {
            unsigned long long dx2 = add2(cxx, npx[m]);   // cx - px (exact)
            unsigned long long dy2 = add2(cyy, npy[m]);
            unsigned long long dz2 = add2(czz, npz[m]);
            unsigned long long d2p = add2(add2(mul2(dx2, dx2), mul2(dy2, dy2)),
                                          mul2(dz2, dz2)); // ((x²+y²)+z²) rn
            float d0, d1;
            unpack2(d2p, d0, d1);
            dist[2 * m]     = fminf(dist[2 * m], d0);
            dist[2 * m + 1] = fminf(dist[2 * m + 1], d1);
        }

        // ---- per-thread tree max (depth 5) ----
        float t[16];
#pragma unroll
        for (int j = 0; j < 16; j++) t[j] = fmaxf(dist[j], dist[j + 16]);
#pragma unroll
        for (int st = 8; st; st >>= 1)
#pragma unroll
            for (int j = 0; j < 8; j++)
                if (j < st) t[j] = fmaxf(t[j], t[j + st]);
        // warp max: all dists >= 0 -> float bits are int-monotone
        const int wmaxi = __reduce_max_sync(0xffffffffu, __float_as_int(t[0]));

        if (lane == 0) sVal[pb][wid] = wmaxi;
        __syncthreads();

        // block max (every thread, 8 slots)
        int bmax = sVal[pb][0];
#pragma unroll
        for (int w = 1; w < 8; w++) bmax = max(bmax, sVal[pb][w]);

        // ---- phase B: only matching warps recover the lowest index ----
        if (wmaxi == bmax) {
            int c[16];
#pragma unroll
            for (int j = 0; j < 16; j++) {
                int c0 = (__float_as_int(dist[j])      == bmax) ? (j * 256 + tid)        : 0x7FFFFFFF;
                int c1 = (__float_as_int(dist[j + 16]) == bmax) ? ((j + 16) * 256 + tid) : 0x7FFFFFFF;
                c[j] = min(c0, c1);
            }
#pragma unroll
            for (int st = 8; st; st >>= 1)
#pragma unroll
                for (int j = 0; j < 8; j++)
                    if (j < st) c[j] = min(c[j], c[j + st]);
            int wmin = __reduce_min_sync(0xffffffffu, c[0]);
            if (lane == 0) atomicMin(&sIdx[pb], wmin);
        }
        __syncthreads();

        const int xi = sIdx[pb];
        cx = __ldg(P + xi * 3 + 0);   // L1-resident broadcast
        cy = __ldg(P + xi * 3 + 1);
        cz = __ldg(P + xi * 3 + 2);
    }
}

// ---------------------------------------------------------------------------
// Kernel 2 (R8 version — measured 459us): fused ball-query + 3-layer MLP +
// max-pool. One warp per TWO adjacent centers: a single weight LDS.128
// broadcast feeds both centers' FMA2s. BQ scans both centers in one pass.
// Adjacent outputs merged into one STG.64.
// ---------------------------------------------------------------------------
__global__ __launch_bounds__(128) void bq_mlp_kernel(
    const float* __restrict__ xyz,
    const float* __restrict__ w1, const float* __restrict__ b1,
    const float* __restrict__ w2, const float* __restrict__ b2,
    const float* __restrict__ w3, const float* __restrict__ b3,
    float* __restrict__ out)
{
    extern __shared__ float sh[];
    float* sW1  = sh;                    // 192
    float* sB1  = sW1 + C1 * 3;          // 64
    float* sW2t = sB1 + C1;              // 4096 (transposed: [i][o])
    float* sB2  = sW2t + C2 * C1;        // 64
    float* sW3  = sB2 + C2;              // 8192
    float* sB3  = sW3 + C3 * C2;         // 128
    int*   sNbrAll = (int*)(sB3 + C3);   // 4 warps * 2 * 32

    const int tid = threadIdx.x;
    for (int i = tid; i < C1 * 3;  i += 128) sW1[i] = w1[i];
    for (int i = tid; i < C1;      i += 128) sB1[i] = b1[i];
    for (int i = tid; i < C2 * C1; i += 128) {
        int o = i >> 6, ii = i & 63;
        sW2t[ii * C2 + o] = w2[i];
    }
    for (int i = tid; i < C2;      i += 128) sB2[i] = b2[i];
    for (int i = tid; i < C3 * C2; i += 128) sW3[i] = w3[i];
    for (int i = tid; i < C3;      i += 128) sB3[i] = b3[i];
    __syncthreads();

    const int wid  = tid >> 5;
    const int lane = tid & 31;
    const int c0   = blockIdx.x * 8 + wid * 2;  // even; c1 = c0+1 same batch
    const int b    = c0 >> 11;
    const int s0   = c0 & (NS - 1);
    const float* P = xyz + b * NPTS * 3;

    const float cx0 = g_new_xyz[c0 * 3 + 0];
    const float cy0 = g_new_xyz[c0 * 3 + 1];
    const float cz0 = g_new_xyz[c0 * 3 + 2];
    const float cx1 = g_new_xyz[c0 * 3 + 3];
    const float cy1 = g_new_xyz[c0 * 3 + 4];
    const float cz1 = g_new_xyz[c0 * 3 + 5];

    // ---- ball query for both centers in ONE pass (first KNB, ascending) ----
    const float RR = 0.04f;   // JAX weak-typed (0.2*0.2) double -> f32
    int* nb0 = sNbrAll + wid * 2 * KNB;
    int* nb1 = nb0 + KNB;
    int cnt0 = 0, cnt1 = 0;
    const unsigned lm = (1u << lane) - 1u;
    for (int basei = 0; basei < NPTS && (cnt0 < KNB || cnt1 < KNB); basei += 32) {
        int i = basei + lane;
        float px = P[i * 3 + 0], py = P[i * 3 + 1], pz = P[i * 3 + 2];
        float d20 = sqdist_xla(cx0 - px, cy0 - py, cz0 - pz);
        float d21 = sqdist_xla(cx1 - px, cy1 - py, cz1 - pz);
        bool h0 = (d20 <= RR), h1 = (d21 <= RR);
        unsigned m0 = __ballot_sync(0xffffffffu, h0);
        unsigned m1 = __ballot_sync(0xffffffffu, h1);
        int p0 = cnt0 + __popc(m0 & lm);
        int p1 = cnt1 + __popc(m1 & lm);
        if (h0 && p0 < KNB) nb0[p0] = i;
        if (h1 && p1 < KNB) nb1[p1] = i;
        cnt0 += __popc(m0);
        cnt1 += __popc(m1);
    }
    __syncwarp();
    int cc0 = cnt0 < KNB ? cnt0 : KNB;
    int cc1 = cnt1 < KNB ? cnt1 : KNB;
    if (lane >= cc0) nb0[lane] = nb0[0];
    if (lane >= cc1) nb1[lane] = nb1[0];
    __syncwarp();
    const int ni0 = nb0[lane];
    const int ni1 = nb1[lane];

    const float rx0 = P[ni0 * 3 + 0] - cx0;
    const float ry0 = P[ni0 * 3 + 1] - cy0;
    const float rz0 = P[ni0 * 3 + 2] - cz0;
    const float rx1 = P[ni1 * 3 + 0] - cx1;
    const float ry1 = P[ni1 * 3 + 1] - cy1;
    const float rz1 = P[ni1 * 3 + 2] - cz1;

    // ---- layers 1+2 fused for BOTH centers (weights loaded once) ----
    unsigned long long acc0[C2 / 2], acc1[C2 / 2];
    {
        const ulonglong2* b2p = reinterpret_cast<const ulonglong2*>(sB2);
#pragma unroll
        for (int j = 0; j < C2 / 4; j++) {
            ulonglong2 v = b2p[j];
            acc0[2 * j] = v.x;  acc0[2 * j + 1] = v.y;
            acc1[2 * j] = v.x;  acc1[2 * j + 1] = v.y;
        }
    }
#pragma unroll 2
    for (int i = 0; i < C1; i++) {
        float a0 = sB1[i], a1 = sB1[i];
        float wx = sW1[i * 3 + 0], wy = sW1[i * 3 + 1], wz = sW1[i * 3 + 2];
        a0 = fmaf(wx, rx0, a0); a0 = fmaf(wy, ry0, a0); a0 = fmaf(wz, rz0, a0);
        a1 = fmaf(wx, rx1, a1); a1 = fmaf(wy, ry1, a1); a1 = fmaf(wz, rz1, a1);
        unsigned long long h0p = pack2(fmaxf(a0, 0.0f), fmaxf(a0, 0.0f));
        unsigned long long h1p = pack2(fmaxf(a1, 0.0f), fmaxf(a1, 0.0f));
        const ulonglong2* w4 = reinterpret_cast<const ulonglong2*>(sW2t + (i << 6));
#pragma unroll
        for (int j = 0; j < C2 / 4; j++) {
            ulonglong2 w = w4[j];                    // ONE LDS feeds both centers
            acc0[2 * j]     = fma2(w.x, h0p, acc0[2 * j]);
            acc0[2 * j + 1] = fma2(w.y, h0p, acc0[2 * j + 1]);
            acc1[2 * j]     = fma2(w.x, h1p, acc1[2 * j]);
            acc1[2 * j + 1] = fma2(w.y, h1p, acc1[2 * j + 1]);
        }
    }
#pragma unroll
    for (int j = 0; j < C2 / 2; j++) {
        float a0, a1;
        unpack2(acc0[j], a0, a1);
        acc0[j] = pack2(fmaxf(a0, 0.0f), fmaxf(a1, 0.0f));
        unpack2(acc1[j], a0, a1);
        acc1[j] = pack2(fmaxf(a0, 0.0f), fmaxf(a1, 0.0f));
    }

    // ---- layer 3 for both centers, warp max, STG.64 merged output ----
    float* optr = out + BATCH * 3 * NS + (b * C3) * NS + s0;
#pragma unroll 2
    for (int o = 0; o < C3; o++) {
        const ulonglong2* w4 = reinterpret_cast<const ulonglong2*>(sW3 + (o << 6));
        unsigned long long s0a = pack2(0.0f, 0.0f), s0b = pack2(0.0f, 0.0f);
        unsigned long long s1a = pack2(0.0f, 0.0f), s1b = pack2(0.0f, 0.0f);
#pragma unroll
        for (int j = 0; j < C2 / 4; j++) {
            ulonglong2 w = w4[j];                    // ONE LDS feeds both centers
            s0a = fma2(w.x, acc0[2 * j],     s0a);
            s0b = fma2(w.y, acc0[2 * j + 1], s0b);
            s1a = fma2(w.x, acc1[2 * j],     s1a);
            s1b = fma2(w.y, acc1[2 * j + 1], s1b);
        }
        float p0, p1, q0, q1;
        unpack2(s0a, p0, p1); unpack2(s0b, q0, q1);
        float a0 = ((p0 + p1) + (q0 + q1)) + sB3[o];
        unpack2(s1a, p0, p1); unpack2(s1b, q0, q1);
        float a1 = ((p0 + p1) + (q0 + q1)) + sB3[o];
        a0 = fmaxf(a0, 0.0f);
        a1 = fmaxf(a1, 0.0f);
#pragma unroll
        for (int off = 16; off; off >>= 1) {
            a0 = fmaxf(a0, __shfl_xor_sync(0xffffffffu, a0, off));
            a1 = fmaxf(a1, __shfl_xor_sync(0xffffffffu, a1, off));
        }
        if (lane == 0) {
            float2 v = make_float2(a0, a1);          // s0 even -> 8B aligned
            *reinterpret_cast<float2*>(optr + o * NS) = v;
        }
    }
}

// ---------------------------------------------------------------------------
extern "C" void kernel_launch(void* const* d_in, const int* in_sizes, int n_in,
                              void* d_out, int out_size)
{
    const float* xyz = (const float*)d_in[0];
    // d_in[1] = features, unused by the reference
    const float* w1 = (const float*)d_in[2];
    const float* b1 = (const float*)d_in[3];
    const float* w2 = (const float*)d_in[4];
    const float* b2 = (const float*)d_in[5];
    const float* w3 = (const float*)d_in[6];
    const float* b3 = (const float*)d_in[7];
    float* out = (float*)d_out;

    const int shmem = (C1 * 3 + C1 + C2 * C1 + C2 + C3 * C2 + C3) * 4
                    + 4 * 2 * KNB * 4;
    cudaFuncSetAttribute(bq_mlp_kernel, cudaFuncAttributeMaxDynamicSharedMemorySize, shmem);

    fps_kernel<<<BATCH, 256>>>(xyz, out);
    bq_mlp_kernel<<<(BATCH * NS) / 8, 128, shmem>>>(xyz, w1, b1, w2, b2, w3, b3, out);
}

// round 10
// speedup vs baseline: 1.5782x; 1.5782x over previous
#include <cuda_runtime.h>
#include <cstdint>

#define BATCH 8
#define NPTS  8192
#define NS    2048      // S = 0.25 * N
#define KNB   32        // nsample
#define C1    64
#define C2    64
#define C3    128

// scratch: new_xyz coords shared between the two kernels
__device__ float g_new_xyz[BATCH * NS * 3];

// XLA-exact squared distance: ((dx*dx + dy*dy) + dz*dz), no FMA contraction
__device__ __forceinline__ float sqdist_xla(float dx, float dy, float dz) {
    return __fadd_rn(__fadd_rn(__fmul_rn(dx, dx), __fmul_rn(dy, dy)),
                     __fmul_rn(dz, dz));
}

__device__ __forceinline__ unsigned long long pack2(float a, float b) {
    unsigned long long r;
    asm("mov.b64 %0, {%1, %2};" : "=l"(r) : "f"(a), "f"(b));
    return r;
}
__device__ __forceinline__ void unpack2(unsigned long long v, float& a, float& b) {
    asm("mov.b64 {%0, %1}, %2;" : "=f"(a), "=f"(b) : "l"(v));
}
__device__ __forceinline__ unsigned long long add2(unsigned long long a, unsigned long long b) {
    unsigned long long r;
    asm("add.rn.f32x2 %0, %1, %2;" : "=l"(r) : "l"(a), "l"(b));
    return r;
}
__device__ __forceinline__ unsigned long long mul2(unsigned long long a, unsigned long long b) {
    unsigned long long r;
    asm("mul.rn.f32x2 %0, %1, %2;" : "=l"(r) : "l"(a), "l"(b));
    return r;
}
__device__ __forceinline__ unsigned long long fma2(unsigned long long a, unsigned long long b,
                                                   unsigned long long c) {
    unsigned long long r;
    asm("fma.rn.f32x2 %0, %1, %2, %3;" : "=l"(r) : "l"(a), "l"(b), "l"(c));
    return r;
}

// warp max of a non-negative float via REDUX (bits are uint-monotone for >=0)
__device__ __forceinline__ float warp_max_nonneg(float v) {
    return __uint_as_float(__reduce_max_sync(0xffffffffu, __float_as_uint(v)));
}

// ---------------------------------------------------------------------------
// Kernel 1: farthest point sampling (R7 version — measured 1180us on the
// fast node; single-SM fma-pipe issue floor). One CTA (256 threads) per batch.
// ---------------------------------------------------------------------------
__global__ __launch_bounds__(256) void fps_kernel(const float* __restrict__ xyz,
                                                  float* __restrict__ out)
{
    const int b   = blockIdx.x;
    const int tid = threadIdx.x;
    const int lane = tid & 31, wid = tid >> 5;
    const float* P = xyz + b * NPTS * 3;

    __shared__ int sVal[2][8];   // per-warp max (float bits)
    __shared__ int sIdx[2];      // block argmin index (atomicMin target)

    unsigned long long npx[16], npy[16], npz[16];
    float dist[32];
#pragma unroll
    for (int m = 0; m < 16; m++) {
        int i0 = tid + (2 * m) * 256;
        int i1 = tid + (2 * m + 1) * 256;
        npx[m] = pack2(-P[i0 * 3 + 0], -P[i1 * 3 + 0]);
        npy[m] = pack2(-P[i0 * 3 + 1], -P[i1 * 3 + 1]);
        npz[m] = pack2(-P[i0 * 3 + 2], -P[i1 * 3 + 2]);
        dist[2 * m] = 1e10f;
        dist[2 * m + 1] = 1e10f;
    }
    float cx = __ldg(P + 0), cy = __ldg(P + 1), cz = __ldg(P + 2);

    for (int s = 0; s < NS; s++) {
        const int pb = s & 1;
        if (tid == 0) {
            int o = b * 3 * NS + s;          // (B,3,S) transposed output
            out[o]          = cx;
            out[o + NS]     = cy;
            out[o + 2 * NS] = cz;
            int c = (b * NS + s) * 3;
            g_new_xyz[c]     = cx;
            g_new_xyz[c + 1] = cy;
            g_new_xyz[c + 2] = cz;
            sIdx[pb] = 0x7FFFFFFF;
        }

        const unsigned long long cxx = pack2(cx, cx);
        const unsigned long long cyy = pack2(cy, cy);
        const unsigned long long czz = pack2(cz, cz);

        // ---- dist update (bit-exact, no index tracking) ----
#pragma unroll
        for (int m = 0; m < 16; m++) {
            unsigned long long dx2 = add2(cxx, npx[m]);   // cx - px (exact)
            unsigned long long dy2 = add2(cyy, npy[m]);
            unsigned long long dz2 = add2(czz, npz[m]);
            unsigned long long d2p = add2(add2(mul2(dx2, dx2), mul2(dy2, dy2)),
                                          mul2(dz2, dz2)); // ((x²+y²)+z²) rn
            float d0, d1;
            unpack2(d2p, d0, d1);
            dist[2 * m]     = fminf(dist[2 * m], d0);
            dist[2 * m + 1] = fminf(dist[2 * m + 1], d1);
        }

        // ---- per-thread tree max (depth 5) ----
        float t[16];
#pragma unroll
        for (int j = 0; j < 16; j++) t[j] = fmaxf(dist[j], dist[j + 16]);
#pragma unroll
        for (int st = 8; st; st >>= 1)
#pragma unroll
            for (int j = 0; j < 8; j++)
                if (j < st) t[j] = fmaxf(t[j], t[j + st]);
        // warp max: all dists >= 0 -> float bits are int-monotone
        const int wmaxi = __reduce_max_sync(0xffffffffu, __float_as_int(t[0]));

        if (lane == 0) sVal[pb][wid] = wmaxi;
        __syncthreads();

        // block max (every thread, 8 slots)
        int bmax = sVal[pb][0];
#pragma unroll
        for (int w = 1; w < 8; w++) bmax = max(bmax, sVal[pb][w]);

        // ---- phase B: only matching warps recover the lowest index ----
        if (wmaxi == bmax) {
            int c[16];
#pragma unroll
            for (int j = 0; j < 16; j++) {
                int c0 = (__float_as_int(dist[j])      == bmax) ? (j * 256 + tid)        : 0x7FFFFFFF;
                int c1 = (__float_as_int(dist[j + 16]) == bmax) ? ((j + 16) * 256 + tid) : 0x7FFFFFFF;
                c[j] = min(c0, c1);
            }
#pragma unroll
            for (int st = 8; st; st >>= 1)
#pragma unroll
                for (int j = 0; j < 8; j++)
                    if (j < st) c[j] = min(c[j], c[j + st]);
            int wmin = __reduce_min_sync(0xffffffffu, c[0]);
            if (lane == 0) atomicMin(&sIdx[pb], wmin);
        }
        __syncthreads();

        const int xi = sIdx[pb];
        cx = __ldg(P + xi * 3 + 0);   // L1-resident broadcast
        cy = __ldg(P + xi * 3 + 1);
        cz = __ldg(P + xi * 3 + 2);
    }
}

// ---------------------------------------------------------------------------
// Kernel 2: fused ball-query + 3-layer MLP + max-pool. One warp per TWO
// adjacent centers (shared weight LDS). Layer-3 max-pool now uses a single
// REDUX.MAX per output channel (post-relu values are >= 0 -> uint-monotone)
// instead of a 5-SHFL + 5-FMAX chain: 2560 -> 256 reduction instructions.
// ---------------------------------------------------------------------------
__global__ __launch_bounds__(128) void bq_mlp_kernel(
    const float* __restrict__ xyz,
    const float* __restrict__ w1, const float* __restrict__ b1,
    const float* __restrict__ w2, const float* __restrict__ b2,
    const float* __restrict__ w3, const float* __restrict__ b3,
    float* __restrict__ out)
{
    extern __shared__ float sh[];
    float* sW1  = sh;                    // 192
    float* sB1  = sW1 + C1 * 3;          // 64
    float* sW2t = sB1 + C1;              // 4096 (transposed: [i][o])
    float* sB2  = sW2t + C2 * C1;        // 64
    float* sW3  = sB2 + C2;              // 8192
    float* sB3  = sW3 + C3 * C2;         // 128
    int*   sNbrAll = (int*)(sB3 + C3);   // 4 warps * 2 * 32

    const int tid = threadIdx.x;
    for (int i = tid; i < C1 * 3;  i += 128) sW1[i] = w1[i];
    for (int i = tid; i < C1;      i += 128) sB1[i] = b1[i];
    for (int i = tid; i < C2 * C1; i += 128) {
        int o = i >> 6, ii = i & 63;
        sW2t[ii * C2 + o] = w2[i];
    }
    for (int i = tid; i < C2;      i += 128) sB2[i] = b2[i];
    for (int i = tid; i < C3 * C2; i += 128) sW3[i] = w3[i];
    for (int i = tid; i < C3;      i += 128) sB3[i] = b3[i];
    __syncthreads();

    const int wid  = tid >> 5;
    const int lane = tid & 31;
    const int c0   = blockIdx.x * 8 + wid * 2;  // even; c1 = c0+1 same batch
    const int b    = c0 >> 11;
    const int s0   = c0 & (NS - 1);
    const float* P = xyz + b * NPTS * 3;

    const float cx0 = g_new_xyz[c0 * 3 + 0];
    const float cy0 = g_new_xyz[c0 * 3 + 1];
    const float cz0 = g_new_xyz[c0 * 3 + 2];
    const float cx1 = g_new_xyz[c0 * 3 + 3];
    const float cy1 = g_new_xyz[c0 * 3 + 4];
    const float cz1 = g_new_xyz[c0 * 3 + 5];

    // ---- ball query for both centers in ONE pass (first KNB, ascending) ----
    const float RR = 0.04f;   // JAX weak-typed (0.2*0.2) double -> f32
    int* nb0 = sNbrAll + wid * 2 * KNB;
    int* nb1 = nb0 + KNB;
    int cnt0 = 0, cnt1 = 0;
    const unsigned lm = (1u << lane) - 1u;
    for (int basei = 0; basei < NPTS && (cnt0 < KNB || cnt1 < KNB); basei += 32) {
        int i = basei + lane;
        float px = P[i * 3 + 0], py = P[i * 3 + 1], pz = P[i * 3 + 2];
        float d20 = sqdist_xla(cx0 - px, cy0 - py, cz0 - pz);
        float d21 = sqdist_xla(cx1 - px, cy1 - py, cz1 - pz);
        bool h0 = (d20 <= RR), h1 = (d21 <= RR);
        unsigned m0 = __ballot_sync(0xffffffffu, h0);
        unsigned m1 = __ballot_sync(0xffffffffu, h1);
        int p0 = cnt0 + __popc(m0 & lm);
        int p1 = cnt1 + __popc(m1 & lm);
        if (h0 && p0 < KNB) nb0[p0] = i;
        if (h1 && p1 < KNB) nb1[p1] = i;
        cnt0 += __popc(m0);
        cnt1 += __popc(m1);
    }
    __syncwarp();
    int cc0 = cnt0 < KNB ? cnt0 : KNB;
    int cc1 = cnt1 < KNB ? cnt1 : KNB;
    if (lane >= cc0) nb0[lane] = nb0[0];
    if (lane >= cc1) nb1[lane] = nb1[0];
    __syncwarp();
    const int ni0 = nb0[lane];
    const int ni1 = nb1[lane];

    const float rx0 = P[ni0 * 3 + 0] - cx0;
    const float ry0 = P[ni0 * 3 + 1] - cy0;
    const float rz0 = P[ni0 * 3 + 2] - cz0;
    const float rx1 = P[ni1 * 3 + 0] - cx1;
    const float ry1 = P[ni1 * 3 + 1] - cy1;
    const float rz1 = P[ni1 * 3 + 2] - cz1;

    // ---- layers 1+2 fused for BOTH centers (weights loaded once) ----
    unsigned long long acc0[C2 / 2], acc1[C2 / 2];
    {
        const ulonglong2* b2p = reinterpret_cast<const ulonglong2*>(sB2);
#pragma unroll
        for (int j = 0; j < C2 / 4; j++) {
            ulonglong2 v = b2p[j];
            acc0[2 * j] = v.x;  acc0[2 * j + 1] = v.y;
            acc1[2 * j] = v.x;  acc1[2 * j + 1] = v.y;
        }
    }
#pragma unroll 2
    for (int i = 0; i < C1; i++) {
        float a0 = sB1[i], a1 = sB1[i];
        float wx = sW1[i * 3 + 0], wy = sW1[i * 3 + 1], wz = sW1[i * 3 + 2];
        a0 = fmaf(wx, rx0, a0); a0 = fmaf(wy, ry0, a0); a0 = fmaf(wz, rz0, a0);
        a1 = fmaf(wx, rx1, a1); a1 = fmaf(wy, ry1, a1); a1 = fmaf(wz, rz1, a1);
        unsigned long long h0p = pack2(fmaxf(a0, 0.0f), fmaxf(a0, 0.0f));
        unsigned long long h1p = pack2(fmaxf(a1, 0.0f), fmaxf(a1, 0.0f));
        const ulonglong2* w4 = reinterpret_cast<const ulonglong2*>(sW2t + (i << 6));
#pragma unroll
        for (int j = 0; j < C2 / 4; j++) {
            ulonglong2 w = w4[j];                    // ONE LDS feeds both centers
            acc0[2 * j]     = fma2(w.x, h0p, acc0[2 * j]);
            acc0[2 * j + 1] = fma2(w.y, h0p, acc0[2 * j + 1]);
            acc1[2 * j]     = fma2(w.x, h1p, acc1[2 * j]);
            acc1[2 * j + 1] = fma2(w.y, h1p, acc1[2 * j + 1]);
        }
    }
#pragma unroll
    for (int j = 0; j < C2 / 2; j++) {
        float a0, a1;
        unpack2(acc0[j], a0, a1);
        acc0[j] = pack2(fmaxf(a0, 0.0f), fmaxf(a1, 0.0f));
        unpack2(acc1[j], a0, a1);
        acc1[j] = pack2(fmaxf(a0, 0.0f), fmaxf(a1, 0.0f));
    }

    // ---- layer 3 for both centers, REDUX max-pool, STG.64 merged output ----
    float* optr = out + BATCH * 3 * NS + (b * C3) * NS + s0;
#pragma unroll 2
    for (int o = 0; o < C3; o++) {
        const ulonglong2* w4 = reinterpret_cast<const ulonglong2*>(sW3 + (o << 6));
        unsigned long long s0a = pack2(0.0f, 0.0f), s0b = pack2(0.0f, 0.0f);
        unsigned long long s1a = pack2(0.0f, 0.0f), s1b = pack2(0.0f, 0.0f);
#pragma unroll
        for (int j = 0; j < C2 / 4; j++) {
            ulonglong2 w = w4[j];                    // ONE LDS feeds both centers
            s0a = fma2(w.x, acc0[2 * j],     s0a);
            s0b = fma2(w.y, acc0[2 * j + 1], s0b);
            s1a = fma2(w.x, acc1[2 * j],     s1a);
            s1b = fma2(w.y, acc1[2 * j + 1], s1b);
        }
        float p0, p1, q0, q1;
        unpack2(s0a, p0, p1); unpack2(s0b, q0, q1);
        float a0 = ((p0 + p1) + (q0 + q1)) + sB3[o];
        unpack2(s1a, p0, p1); unpack2(s1b, q0, q1);
        float a1 = ((p0 + p1) + (q0 + q1)) + sB3[o];
        // post-relu values are non-negative -> one REDUX.MAX per channel
        a0 = warp_max_nonneg(fmaxf(a0, 0.0f));
        a1 = warp_max_nonneg(fmaxf(a1, 0.0f));
        if (lane == 0) {
            float2 v = make_float2(a0, a1);          // s0 even -> 8B aligned
            *reinterpret_cast<float2*>(optr + o * NS) = v;
        }
    }
}

// ---------------------------------------------------------------------------
extern "C" void kernel_launch(void* const* d_in, const int* in_sizes, int n_in,
                              void* d_out, int out_size)
{
    const float* xyz = (const float*)d_in[0];
    // d_in[1] = features, unused by the reference
    const float* w1 = (const float*)d_in[2];
    const float* b1 = (const float*)d_in[3];
    const float* w2 = (const float*)d_in[4];
    const float* b2 = (const float*)d_in[5];
    const float* w3 = (const float*)d_in[6];
    const float* b3 = (const float*)d_in[7];
    float* out = (float*)d_out;

    const int shmem = (C1 * 3 + C1 + C2 * C1 + C2 + C3 * C2 + C3) * 4
                    + 4 * 2 * KNB * 4;
    cudaFuncSetAttribute(bq_mlp_kernel, cudaFuncAttributeMaxDynamicSharedMemorySize, shmem);

    fps_kernel<<<BATCH, 256>>>(xyz, out);
    bq_mlp_kernel<<<(BATCH * NS) / 8, 128, shmem>>>(xyz, w1, b1, w2, b2, w3, b3, out);
}

// round 11
// speedup vs baseline: 1.6309x; 1.0334x over previous
#include <cuda_runtime.h>
#include <cstdint>

#define BATCH 8
#define NPTS  8192
#define NS    2048      // S = 0.25 * N
#define KNB   32        // nsample
#define C1    64
#define C2    64
#define C3    128

// scratch: new_xyz coords shared between the two kernels
__device__ float g_new_xyz[BATCH * NS * 3];

// XLA-exact squared distance: ((dx*dx + dy*dy) + dz*dz), no FMA contraction
__device__ __forceinline__ float sqdist_xla(float dx, float dy, float dz) {
    return __fadd_rn(__fadd_rn(__fmul_rn(dx, dx), __fmul_rn(dy, dy)),
                     __fmul_rn(dz, dz));
}

__device__ __forceinline__ unsigned long long pack2(float a, float b) {
    unsigned long long r;
    asm("mov.b64 %0, {%1, %2};" : "=l"(r) : "f"(a), "f"(b));
    return r;
}
__device__ __forceinline__ void unpack2(unsigned long long v, float& a, float& b) {
    asm("mov.b64 {%0, %1}, %2;" : "=f"(a), "=f"(b) : "l"(v));
}
__device__ __forceinline__ unsigned long long add2(unsigned long long a, unsigned long long b) {
    unsigned long long r;
    asm("add.rn.f32x2 %0, %1, %2;" : "=l"(r) : "l"(a), "l"(b));
    return r;
}
__device__ __forceinline__ unsigned long long mul2(unsigned long long a, unsigned long long b) {
    unsigned long long r;
    asm("mul.rn.f32x2 %0, %1, %2;" : "=l"(r) : "l"(a), "l"(b));
    return r;
}
__device__ __forceinline__ unsigned long long fma2(unsigned long long a, unsigned long long b,
                                                   unsigned long long c) {
    unsigned long long r;
    asm("fma.rn.f32x2 %0, %1, %2, %3;" : "=l"(r) : "l"(a), "l"(b), "l"(c));
    return r;
}

// warp max of a non-negative float via REDUX (bits are uint-monotone for >=0)
__device__ __forceinline__ float warp_max_nonneg(float v) {
    return __uint_as_float(__reduce_max_sync(0xffffffffu, __float_as_uint(v)));
}

// ---------------------------------------------------------------------------
// Kernel 1: farthest point sampling. One CTA (512 threads = 4 warps/SMSP)
// per batch — doubled warp count vs R10 to hide the lat-4 f32x2 dependency
// chains and the reduce-tail latencies (prev config measured ~400 cyc/iter
// of bubbles at 2 warps/SMSP). 16 points/thread.
// ---------------------------------------------------------------------------
__global__ __launch_bounds__(512) void fps_kernel(const float* __restrict__ xyz,
                                                  float* __restrict__ out)
{
    const int b   = blockIdx.x;
    const int tid = threadIdx.x;
    const int lane = tid & 31, wid = tid >> 5;
    const float* P = xyz + b * NPTS * 3;

    __shared__ int sVal[2][16];  // per-warp max (float bits), 16 warps
    __shared__ int sIdx[2];      // block argmin index (atomicMin target)

    unsigned long long npx[8], npy[8], npz[8];
    float dist[16];
#pragma unroll
    for (int m = 0; m < 8; m++) {
        int i0 = tid + (2 * m) * 512;
        int i1 = tid + (2 * m + 1) * 512;
        npx[m] = pack2(-P[i0 * 3 + 0], -P[i1 * 3 + 0]);
        npy[m] = pack2(-P[i0 * 3 + 1], -P[i1 * 3 + 1]);
        npz[m] = pack2(-P[i0 * 3 + 2], -P[i1 * 3 + 2]);
        dist[2 * m] = 1e10f;
        dist[2 * m + 1] = 1e10f;
    }
    float cx = __ldg(P + 0), cy = __ldg(P + 1), cz = __ldg(P + 2);

    for (int s = 0; s < NS; s++) {
        const int pb = s & 1;
        if (tid == 0) {
            int o = b * 3 * NS + s;          // (B,3,S) transposed output
            out[o]          = cx;
            out[o + NS]     = cy;
            out[o + 2 * NS] = cz;
            int c = (b * NS + s) * 3;
            g_new_xyz[c]     = cx;
            g_new_xyz[c + 1] = cy;
            g_new_xyz[c + 2] = cz;
            sIdx[pb] = 0x7FFFFFFF;
        }

        const unsigned long long cxx = pack2(cx, cx);
        const unsigned long long cyy = pack2(cy, cy);
        const unsigned long long czz = pack2(cz, cz);

        // ---- dist update (bit-exact rn, fma-pipe) + fmin (alu-pipe) ----
#pragma unroll
        for (int m = 0; m < 8; m++) {
            unsigned long long dx2 = add2(cxx, npx[m]);   // cx - px (exact)
            unsigned long long dy2 = add2(cyy, npy[m]);
            unsigned long long dz2 = add2(czz, npz[m]);
            unsigned long long d2p = add2(add2(mul2(dx2, dx2), mul2(dy2, dy2)),
                                          mul2(dz2, dz2)); // ((x²+y²)+z²) rn
            float d0, d1;
            unpack2(d2p, d0, d1);
            dist[2 * m]     = fminf(dist[2 * m], d0);
            dist[2 * m + 1] = fminf(dist[2 * m + 1], d1);
        }

        // ---- per-thread tree max (depth 4) ----
        float t[8];
#pragma unroll
        for (int j = 0; j < 8; j++) t[j] = fmaxf(dist[j], dist[j + 8]);
#pragma unroll
        for (int st = 4; st; st >>= 1)
#pragma unroll
            for (int j = 0; j < 4; j++)
                if (j < st) t[j] = fmaxf(t[j], t[j + st]);
        // warp max: all dists >= 0 -> float bits are int-monotone
        const int wmaxi = __reduce_max_sync(0xffffffffu, __float_as_int(t[0]));

        if (lane == 0) sVal[pb][wid] = wmaxi;
        __syncthreads();

        // block max (every thread, 16 slots via 4x LDS.128)
        const int4* sv4 = reinterpret_cast<const int4*>(sVal[pb]);
        int4 v0 = sv4[0], v1 = sv4[1], v2 = sv4[2], v3 = sv4[3];
        int bmax = max(max(max(v0.x, v0.y), max(v0.z, v0.w)),
                       max(max(v1.x, v1.y), max(v1.z, v1.w)));
        bmax = max(bmax, max(max(max(v2.x, v2.y), max(v2.z, v2.w)),
                             max(max(v3.x, v3.y), max(v3.z, v3.w))));

        // ---- phase B: only matching warps recover the lowest index ----
        if (wmaxi == bmax) {
            int c[8];
#pragma unroll
            for (int j = 0; j < 8; j++) {
                int c0 = (__float_as_int(dist[j])     == bmax) ? (j * 512 + tid)       : 0x7FFFFFFF;
                int c1 = (__float_as_int(dist[j + 8]) == bmax) ? ((j + 8) * 512 + tid) : 0x7FFFFFFF;
                c[j] = min(c0, c1);
            }
#pragma unroll
            for (int st = 4; st; st >>= 1)
#pragma unroll
                for (int j = 0; j < 4; j++)
                    if (j < st) c[j] = min(c[j], c[j + st]);
            int wmin = __reduce_min_sync(0xffffffffu, c[0]);
            if (lane == 0) atomicMin(&sIdx[pb], wmin);
        }
        __syncthreads();

        const int xi = sIdx[pb];
        cx = __ldg(P + xi * 3 + 0);   // L1-resident broadcast
        cy = __ldg(P + xi * 3 + 1);
        cz = __ldg(P + xi * 3 + 2);
    }
}

// ---------------------------------------------------------------------------
// Kernel 2 (R10 version — measured 445us): fused ball-query + 3-layer MLP +
// max-pool. One warp per TWO adjacent centers (shared weight LDS), REDUX
// max-pool, STG.64 merged output. UNCHANGED.
// ---------------------------------------------------------------------------
__global__ __launch_bounds__(128) void bq_mlp_kernel(
    const float* __restrict__ xyz,
    const float* __restrict__ w1, const float* __restrict__ b1,
    const float* __restrict__ w2, const float* __restrict__ b2,
    const float* __restrict__ w3, const float* __restrict__ b3,
    float* __restrict__ out)
{
    extern __shared__ float sh[];
    float* sW1  = sh;                    // 192
    float* sB1  = sW1 + C1 * 3;          // 64
    float* sW2t = sB1 + C1;              // 4096 (transposed: [i][o])
    float* sB2  = sW2t + C2 * C1;        // 64
    float* sW3  = sB2 + C2;              // 8192
    float* sB3  = sW3 + C3 * C2;         // 128
    int*   sNbrAll = (int*)(sB3 + C3);   // 4 warps * 2 * 32

    const int tid = threadIdx.x;
    for (int i = tid; i < C1 * 3;  i += 128) sW1[i] = w1[i];
    for (int i = tid; i < C1;      i += 128) sB1[i] = b1[i];
    for (int i = tid; i < C2 * C1; i += 128) {
        int o = i >> 6, ii = i & 63;
        sW2t[ii * C2 + o] = w2[i];
    }
    for (int i = tid; i < C2;      i += 128) sB2[i] = b2[i];
    for (int i = tid; i < C3 * C2; i += 128) sW3[i] = w3[i];
    for (int i = tid; i < C3;      i += 128) sB3[i] = b3[i];
    __syncthreads();

    const int wid  = tid >> 5;
    const int lane = tid & 31;
    const int c0   = blockIdx.x * 8 + wid * 2;  // even; c1 = c0+1 same batch
    const int b    = c0 >> 11;
    const int s0   = c0 & (NS - 1);
    const float* P = xyz + b * NPTS * 3;

    const float cx0 = g_new_xyz[c0 * 3 + 0];
    const float cy0 = g_new_xyz[c0 * 3 + 1];
    const float cz0 = g_new_xyz[c0 * 3 + 2];
    const float cx1 = g_new_xyz[c0 * 3 + 3];
    const float cy1 = g_new_xyz[c0 * 3 + 4];
    const float cz1 = g_new_xyz[c0 * 3 + 5];

    // ---- ball query for both centers in ONE pass (first KNB, ascending) ----
    const float RR = 0.04f;   // JAX weak-typed (0.2*0.2) double -> f32
    int* nb0 = sNbrAll + wid * 2 * KNB;
    int* nb1 = nb0 + KNB;
    int cnt0 = 0, cnt1 = 0;
    const unsigned lm = (1u << lane) - 1u;
    for (int basei = 0; basei < NPTS && (cnt0 < KNB || cnt1 < KNB); basei += 32) {
        int i = basei + lane;
        float px = P[i * 3 + 0], py = P[i * 3 + 1], pz = P[i * 3 + 2];
        float d20 = sqdist_xla(cx0 - px, cy0 - py, cz0 - pz);
        float d21 = sqdist_xla(cx1 - px, cy1 - py, cz1 - pz);
        bool h0 = (d20 <= RR), h1 = (d21 <= RR);
        unsigned m0 = __ballot_sync(0xffffffffu, h0);
        unsigned m1 = __ballot_sync(0xffffffffu, h1);
        int p0 = cnt0 + __popc(m0 & lm);
        int p1 = cnt1 + __popc(m1 & lm);
        if (h0 && p0 < KNB) nb0[p0] = i;
        if (h1 && p1 < KNB) nb1[p1] = i;
        cnt0 += __popc(m0);
        cnt1 += __popc(m1);
    }
    __syncwarp();
    int cc0 = cnt0 < KNB ? cnt0 : KNB;
    int cc1 = cnt1 < KNB ? cnt1 : KNB;
    if (lane >= cc0) nb0[lane] = nb0[0];
    if (lane >= cc1) nb1[lane] = nb1[0];
    __syncwarp();
    const int ni0 = nb0[lane];
    const int ni1 = nb1[lane];

    const float rx0 = P[ni0 * 3 + 0] - cx0;
    const float ry0 = P[ni0 * 3 + 1] - cy0;
    const float rz0 = P[ni0 * 3 + 2] - cz0;
    const float rx1 = P[ni1 * 3 + 0] - cx1;
    const float ry1 = P[ni1 * 3 + 1] - cy1;
    const float rz1 = P[ni1 * 3 + 2] - cz1;

    // ---- layers 1+2 fused for BOTH centers (weights loaded once) ----
    unsigned long long acc0[C2 / 2], acc1[C2 / 2];
    {
        const ulonglong2* b2p = reinterpret_cast<const ulonglong2*>(sB2);
#pragma unroll
        for (int j = 0; j < C2 / 4; j++) {
            ulonglong2 v = b2p[j];
            acc0[2 * j] = v.x;  acc0[2 * j + 1] = v.y;
            acc1[2 * j] = v.x;  acc1[2 * j + 1] = v.y;
        }
    }
#pragma unroll 2
    for (int i = 0; i < C1; i++) {
        float a0 = sB1[i], a1 = sB1[i];
        float wx = sW1[i * 3 + 0], wy = sW1[i * 3 + 1], wz = sW1[i * 3 + 2];
        a0 = fmaf(wx, rx0, a0); a0 = fmaf(wy, ry0, a0); a0 = fmaf(wz, rz0, a0);
        a1 = fmaf(wx, rx1, a1); a1 = fmaf(wy, ry1, a1); a1 = fmaf(wz, rz1, a1);
        unsigned long long h0p = pack2(fmaxf(a0, 0.0f), fmaxf(a0, 0.0f));
        unsigned long long h1p = pack2(fmaxf(a1, 0.0f), fmaxf(a1, 0.0f));
        const ulonglong2* w4 = reinterpret_cast<const ulonglong2*>(sW2t + (i << 6));
#pragma unroll
        for (int j = 0; j < C2 / 4; j++) {
            ulonglong2 w = w4[j];                    // ONE LDS feeds both centers
            acc0[2 * j]     = fma2(w.x, h0p, acc0[2 * j]);
            acc0[2 * j + 1] = fma2(w.y, h0p, acc0[2 * j + 1]);
            acc1[2 * j]     = fma2(w.x, h1p, acc1[2 * j]);
            acc1[2 * j + 1] = fma2(w.y, h1p, acc1[2 * j + 1]);
        }
    }
#pragma unroll
    for (int j = 0; j < C2 / 2; j++) {
        float a0, a1;
        unpack2(acc0[j], a0, a1);
        acc0[j] = pack2(fmaxf(a0, 0.0f), fmaxf(a1, 0.0f));
        unpack2(acc1[j], a0, a1);
        acc1[j] = pack2(fmaxf(a0, 0.0f), fmaxf(a1, 0.0f));
    }

    // ---- layer 3 for both centers, REDUX max-pool, STG.64 merged output ----
    float* optr = out + BATCH * 3 * NS + (b * C3) * NS + s0;
#pragma unroll 2
    for (int o = 0; o < C3; o++) {
        const ulonglong2* w4 = reinterpret_cast<const ulonglong2*>(sW3 + (o << 6));
        unsigned long long s0a = pack2(0.0f, 0.0f), s0b = pack2(0.0f, 0.0f);
        unsigned long long s1a = pack2(0.0f, 0.0f), s1b = pack2(0.0f, 0.0f);
#pragma unroll
        for (int j = 0; j < C2 / 4; j++) {
            ulonglong2 w = w4[j];                    // ONE LDS feeds both centers
            s0a = fma2(w.x, acc0[2 * j],     s0a);
            s0b = fma2(w.y, acc0[2 * j + 1], s0b);
            s1a = fma2(w.x, acc1[2 * j],     s1a);
            s1b = fma2(w.y, acc1[2 * j + 1], s1b);
        }
        float p0, p1, q0, q1;
        unpack2(s0a, p0, p1); unpack2(s0b, q0, q1);
        float a0 = ((p0 + p1) + (q0 + q1)) + sB3[o];
        unpack2(s1a, p0, p1); unpack2(s1b, q0, q1);
        float a1 = ((p0 + p1) + (q0 + q1)) + sB3[o];
        // post-relu values are non-negative -> one REDUX.MAX per channel
        a0 = warp_max_nonneg(fmaxf(a0, 0.0f));
        a1 = warp_max_nonneg(fmaxf(a1, 0.0f));
        if (lane == 0) {
            float2 v = make_float2(a0, a1);          // s0 even -> 8B aligned
            *reinterpret_cast<float2*>(optr + o * NS) = v;
        }
    }
}

// ---------------------------------------------------------------------------
extern "C" void kernel_launch(void* const* d_in, const int* in_sizes, int n_in,
                              void* d_out, int out_size)
{
    const float* xyz = (const float*)d_in[0];
    // d_in[1] = features, unused by the reference
    const float* w1 = (const float*)d_in[2];
    const float* b1 = (const float*)d_in[3];
    const float* w2 = (const float*)d_in[4];
    const float* b2 = (const float*)d_in[5];
    const float* w3 = (const float*)d_in[6];
    const float* b3 = (const float*)d_in[7];
    float* out = (float*)d_out;

    const int shmem = (C1 * 3 + C1 + C2 * C1 + C2 + C3 * C2 + C3) * 4
                    + 4 * 2 * KNB * 4;
    cudaFuncSetAttribute(bq_mlp_kernel, cudaFuncAttributeMaxDynamicSharedMemorySize, shmem);

    fps_kernel<<<BATCH, 512>>>(xyz, out);
    bq_mlp_kernel<<<(BATCH * NS) / 8, 128, shmem>>>(xyz, w1, b1, w2, b2, w3, b3, out);
}